// round 16
// baseline (speedup 1.0000x reference)
#include <cuda_runtime.h>
#include <cuda_bf16.h>
#include <math.h>
#include <stdint.h>

// Problem constants
#define TT 20
#define DIN 4
#define HH 768
#define BB 1024
#define G4 (4*HH)           // 3072
#define BE_BSTRIDE (TT*HH)  // 15360
#define BP_BSTRIDE (TT*DIN) // 80
#define NBLK 296            // total blocks (2/SM x 148 SMs)
#define NSTEP 256           // step blocks: 6 units each (1536 = 6*256)
#define NGRP 32             // hsum partial slots (bid>>3, step blocks)
#define NQ (G4 + BB)        // per-t prep items: 4096 (divisible by 64)
#define MAXU 6
#define NTILE 192           // step-0 gemm tiles

// ---------------- device scratch ----------------
__device__ float  d_ct[HH * BB];           // c handoff from step-0, [h][b]
__device__ float2 d_rb[TT * G4];           // {rowsum, biassum} packed
__device__ float4 d_bpT[TT * BB];          // batch_price transposed [t][b]
__device__ float  d_evsum[TT];
__device__ float  d_hsum0;
__device__ float  d_hpart[TT * NGRP];
__device__ unsigned d_barcnt;              // step-block barrier counter
__device__ unsigned d_gctr;                // gemm tile queue
__device__ unsigned d_pq[TT];              // per-t prep grab counters
__device__ unsigned d_pfin[TT];            // per-t prep completion counters
__device__ unsigned d_done;

// ---------------- helpers ----------------
__device__ __forceinline__ float fast_sigmoid(float x) {
    return __fdividef(1.0f, 1.0f + __expf(-x));
}
__device__ __forceinline__ float fast_tanh(float x) {
    return __fdividef(2.0f, 1.0f + __expf(-2.0f * x)) - 1.0f;
}
__device__ __forceinline__ float tanh_mufu(float x) {
    float r; asm("tanh.approx.f32 %0, %1;" : "=f"(r) : "f"(x)); return r;
}
__device__ __forceinline__ float sig_mufu(float x) {
    return fmaf(tanh_mufu(x * 0.5f), 0.5f, 0.5f);
}
__device__ __forceinline__ uint32_t f2tf32(float f) {
    uint32_t r; asm("cvt.rna.tf32.f32 %0, %1;" : "=r"(r) : "f"(f)); return r;
}
__device__ __forceinline__ uint32_t smem_u32(const void* p) {
    return (uint32_t)__cvta_generic_to_shared(p);
}
__device__ __forceinline__ void cp_async16(uint32_t dst, const void* src) {
    asm volatile("cp.async.ca.shared.global [%0], [%1], 16;" :: "r"(dst), "l"(src));
}
__device__ __forceinline__ void cp_async8(uint32_t dst, const void* src) {
    asm volatile("cp.async.ca.shared.global [%0], [%1], 8;" :: "r"(dst), "l"(src));
}
__device__ __forceinline__ void cp_async4(uint32_t dst, const void* src) {
    asm volatile("cp.async.ca.shared.global [%0], [%1], 4;" :: "r"(dst), "l"(src));
}
__device__ __forceinline__ void cp_commit() {
    asm volatile("cp.async.commit_group;");
}
template<int N>
__device__ __forceinline__ void cp_wait() {
    asm volatile("cp.async.wait_group %0;" :: "n"(N));
}
__device__ __forceinline__ float blockReduce256(float v) {
    __shared__ float red[8];
    int lane = threadIdx.x & 31, wid = threadIdx.x >> 5;
#pragma unroll
    for (int o = 16; o; o >>= 1) v += __shfl_down_sync(0xffffffffu, v, o);
    if (lane == 0) red[wid] = v;
    __syncthreads();
    if (wid == 0) {
        v = (lane < 8) ? red[lane] : 0.0f;
#pragma unroll
        for (int o = 4; o; o >>= 1) v += __shfl_down_sync(0xffffffffu, v, o);
    }
    __syncthreads();
    return v;
}
__device__ __forceinline__ float sum6f4(const float4 a[6]) {
    float s = 0.0f;
#pragma unroll
    for (int i = 0; i < 6; i++) s += (a[i].x + a[i].y) + (a[i].z + a[i].w);
    return s;
}
__device__ __forceinline__ float warpsum(float s) {
#pragma unroll
    for (int o = 16; o; o >>= 1) s += __shfl_down_sync(0xffffffffu, s, o);
    return s;
}

// ---------------- GEMM tile (tf32 mma), step 0, fused activations ----------
#define GBM 128
#define GBH 32
#define GBN 96
#define GBK 16
#define ASTR 20
#define BSTR 20
#define GSTR 132
#define FUSED_SMEM (GBN * GSTR * 4)   // 50688 B dynamic

__device__ __forceinline__ void gemm_tile(
        int hblk, int mblk,
        const float* __restrict__ be,  const float* __restrict__ whh,
        const float* __restrict__ bp,  const float* __restrict__ wih,
        const float* __restrict__ bih, const float* __restrict__ bhh,
        uint32_t* sm_u) {
    uint32_t* smA = sm_u;
    uint32_t* smB = sm_u + 2 * GBM * ASTR;
    float*    gsm = (float*)sm_u;

    const int tid  = threadIdx.x;
    const int lane = tid & 31;
    const int wid  = tid >> 5;
    const int wm   = wid >> 1;
    const int wn   = wid & 1;
    const int r    = lane >> 2;
    const int cl   = lane & 3;
    const int m0   = mblk * GBM;

    const int arow0 = tid >> 2;
    const int ac4   = tid & 3;
    const int brow  = tid >> 2;
    const int brow2 = (tid + 256) >> 2;
    auto growf = [&] (int row) {
        int q = row >> 5;
        int g = (q == 0) ? 0 : (q == 1 ? 2 : 3);
        return g * HH + hblk * GBH + (row & 31);
    };
    const int grow1 = growf(brow);
    const int grow2 = growf(brow2 < GBN ? brow2 : 0);
    const bool bpred2 = (brow2 < GBN);

    float acc[2][6][4];
#pragma unroll
    for (int i = 0; i < 2; i++)
#pragma unroll
        for (int j = 0; j < 6; j++)
#pragma unroll
            for (int q = 0; q < 4; q++) acc[i][j][q] = 0.0f;

    float4 ra[2], rb[2];
    auto ldg = [&](int kt) {
        ra[0] = *(const float4*)(be + (size_t)(m0 + arow0) * BE_BSTRIDE + kt * GBK + ac4 * 4);
        ra[1] = *(const float4*)(be + (size_t)(m0 + arow0 + 64) * BE_BSTRIDE + kt * GBK + ac4 * 4);
        rb[0] = *(const float4*)(whh + (size_t)grow1 * HH + kt * GBK + ac4 * 4);
        if (bpred2)
            rb[1] = *(const float4*)(whh + (size_t)grow2 * HH + kt * GBK + ac4 * 4);
    };
    auto sts = [&](int buf) {
        uint32_t* pa = smA + buf * (GBM * ASTR);
        uint32_t* pb = smB + buf * (GBN * BSTR);
        uint4 v;
        v.x = f2tf32(ra[0].x); v.y = f2tf32(ra[0].y); v.z = f2tf32(ra[0].z); v.w = f2tf32(ra[0].w);
        *(uint4*)(pa + arow0 * ASTR + ac4 * 4) = v;
        v.x = f2tf32(ra[1].x); v.y = f2tf32(ra[1].y); v.z = f2tf32(ra[1].z); v.w = f2tf32(ra[1].w);
        *(uint4*)(pa + (arow0 + 64) * ASTR + ac4 * 4) = v;
        v.x = f2tf32(rb[0].x); v.y = f2tf32(rb[0].y); v.z = f2tf32(rb[0].z); v.w = f2tf32(rb[0].w);
        *(uint4*)(pb + brow * BSTR + ac4 * 4) = v;
        if (bpred2) {
            v.x = f2tf32(rb[1].x); v.y = f2tf32(rb[1].y); v.z = f2tf32(rb[1].z); v.w = f2tf32(rb[1].w);
            *(uint4*)(pb + brow2 * BSTR + ac4 * 4) = v;
        }
    };

    ldg(0);
    sts(0);
    __syncthreads();

    const int NKT = HH / GBK;   // 48
    for (int kt = 0; kt < NKT; kt++) {
        int buf = kt & 1;
        if (kt < NKT - 1) ldg(kt + 1);

        const uint32_t* pa = smA + buf * (GBM * ASTR);
        const uint32_t* pb = smB + buf * (GBN * BSTR);
#pragma unroll
        for (int kk = 0; kk < 2; kk++) {
            const int kof = kk * 8;
            uint32_t af[2][4], bf[6][2];
#pragma unroll
            for (int i = 0; i < 2; i++) {
                int m = wm * 32 + i * 16 + r;
                af[i][0] = pa[m * ASTR + kof + cl];
                af[i][1] = pa[(m + 8) * ASTR + kof + cl];
                af[i][2] = pa[m * ASTR + kof + cl + 4];
                af[i][3] = pa[(m + 8) * ASTR + kof + cl + 4];
            }
#pragma unroll
            for (int j = 0; j < 6; j++) {
                int n = wn * 48 + j * 8 + r;
                bf[j][0] = pb[n * BSTR + kof + cl];
                bf[j][1] = pb[n * BSTR + kof + cl + 4];
            }
#pragma unroll
            for (int i = 0; i < 2; i++)
#pragma unroll
                for (int j = 0; j < 6; j++) {
                    asm volatile(
                        "mma.sync.aligned.m16n8k8.row.col.f32.tf32.tf32.f32 "
                        "{%0,%1,%2,%3}, {%4,%5,%6,%7}, {%8,%9}, {%0,%1,%2,%3};"
                        : "+f"(acc[i][j][0]), "+f"(acc[i][j][1]),
                          "+f"(acc[i][j][2]), "+f"(acc[i][j][3])
                        : "r"(af[i][0]), "r"(af[i][1]), "r"(af[i][2]), "r"(af[i][3]),
                          "r"(bf[j][0]), "r"(bf[j][1]));
                }
        }
        if (kt < NKT - 1) {
            sts(buf ^ 1);
            __syncthreads();
        }
    }

    __syncthreads();
#pragma unroll
    for (int i = 0; i < 2; i++)
#pragma unroll
        for (int j = 0; j < 6; j++) {
            int m = wm * 32 + i * 16 + r;
            int n = wn * 48 + j * 8 + 2 * cl;
            gsm[n * GSTR + m]           = acc[i][j][0];
            gsm[(n + 1) * GSTR + m]     = acc[i][j][1];
            gsm[n * GSTR + m + 8]       = acc[i][j][2];
            gsm[(n + 1) * GSTR + m + 8] = acc[i][j][3];
        }
    __syncthreads();

    const int m = tid & 127;
    const int b = m0 + m;
    const float4 x = *(const float4*)(bp + (size_t)b * BP_BSTRIDE);  // t=0
    float hpart = 0.0f;
#pragma unroll
    for (int it = 0; it < 16; it++) {
        int hl = (tid >> 7) + it * 2;
        int hg = hblk * GBH + hl;
        int ri = hg, rg = 2 * HH + hg, ro = 3 * HH + hg;
        float4 wi = ((const float4*)wih)[ri];
        float4 wg = ((const float4*)wih)[rg];
        float4 wo = ((const float4*)wih)[ro];
        float gi = gsm[hl * GSTR + m]        + bih[ri] + bhh[ri]
                 + x.x * wi.x + x.y * wi.y + x.z * wi.z + x.w * wi.w;
        float gg = gsm[(hl + 32) * GSTR + m] + bih[rg] + bhh[rg]
                 + x.x * wg.x + x.y * wg.y + x.z * wg.z + x.w * wg.w;
        float go = gsm[(hl + 64) * GSTR + m] + bih[ro] + bhh[ro]
                 + x.x * wo.x + x.y * wo.y + x.z * wo.z + x.w * wo.w;
        float cn = fast_sigmoid(gi) * fast_tanh(gg);   // c_prev = 0, f-gate dead
        d_ct[(size_t)hg * BB + b] = cn;
        hpart += fast_sigmoid(go) * fast_tanh(cn);
    }
    float v = blockReduce256(hpart);
    if (tid == 0) atomicAdd(&d_hsum0, v);
}

// ================= single kernel: step blocks + dedicated prep blocks ======
__global__ __launch_bounds__(256, 2) void fused_kernel(
        const float* __restrict__ bp,  const float* __restrict__ be,
        const float* __restrict__ wih, const float* __restrict__ whh,
        const float* __restrict__ bih, const float* __restrict__ bhh,
        const float* __restrict__ fcw, const float* __restrict__ fcb,
        float* __restrict__ out) {
    extern __shared__ uint32_t sm_u[];
    __shared__ float4 s_w[2][MAXU][4];
    __shared__ float2 s_rb[2][MAXU][4];
    __shared__ float  s_fw[2][MAXU];
    __shared__ float  s_hx;
    __shared__ float  s_ev;
    __shared__ volatile int s_tile;
    __shared__ volatile int s_base;
    __shared__ int    s_lastblk;

    const int tid  = threadIdx.x;
    const int bid  = blockIdx.x;
    const int lane = tid & 31;
    const int wid  = tid >> 5;

    if (bid == 0) {
        float fb = fcb[0];
        for (int i = tid; i < BB; i += 256) out[i] = fb;
    }

    if (bid < NSTEP) {
        // ======================= STEP BLOCK =======================
        // transpose batch_price (step blocks only; visible after pre-barrier)
        for (int idx = bid * 256 + tid; idx < TT * BB; idx += NSTEP * 256) {
            int t = idx >> 10, b = idx & (BB - 1);
            d_bpT[idx] = *(const float4*)(bp + (size_t)b * BP_BSTRIDE + t * DIN);
        }
        __syncthreads();

        // step-0 GEMM tiles, work-stolen among step blocks
        for (;;) {
            if (tid == 0) s_tile = (int)atomicAdd(&d_gctr, 1u);
            __syncthreads();
            int tile = s_tile;
            if (tile >= NTILE) break;
            gemm_tile(tile % 24, tile / 24, be, whh, bp, wih, bih, bhh, sm_u);
            __syncthreads();
        }

        // pre-barrier among the 256 step blocks (epoch 1)
        unsigned epoch = 1;
        __syncthreads();
        if (tid == 0) {
            __threadfence();
            atomicAdd(&d_barcnt, 1u);
            volatile unsigned* p = &d_barcnt;
            while (*p < (unsigned)NSTEP) __nanosleep(32);
            __threadfence();
        }
        __syncthreads();

        const int half = bid & 1;
        const int bI0  = (half << 9) + tid;
        const int bI1  = bI0 + 256;
        const float4* wih4 = (const float4*)wih;

        auto unit_h = [&](int k) -> int {
            return ((k * NSTEP + bid) >> 1);   // = (bid>>1) + k*128
        };
        auto prefetch = [&](int t, int buf) {
            const int base = t * G4;
            if (tid < MAXU * 4) {
                int k = tid >> 2, g = tid & 3;
                cp_async16(smem_u32(&s_w[buf][k][g]), &wih4[base + g * HH + unit_h(k)]);
            } else if (tid >= 32 && tid < 32 + MAXU * 4) {
                int j = tid - 32; int k = j >> 2, g = j & 3;
                cp_async8(smem_u32(&s_rb[buf][k][g]), &d_rb[base + g * HH + unit_h(k)]);
            } else if (tid >= 64 && tid < 64 + MAXU) {
                int k = tid - 64;
                cp_async4(smem_u32(&s_fw[buf][k]), fcw + unit_h(k));
            }
            cp_commit();
        };
        float dt0[MAXU][4], dt1[MAXU][4];
        auto compute_dots = [&](int t, int buf) {
            float4 x0 = d_bpT[(t << 10) + bI0];
            float4 x1 = d_bpT[(t << 10) + bI1];
#pragma unroll
            for (int k = 0; k < MAXU; k++) {
#pragma unroll
                for (int g = 0; g < 4; g++) {
                    float4 w = s_w[buf][k][g];
                    dt0[k][g] = x0.x * w.x + x0.y * w.y + x0.z * w.z + x0.w * w.w;
                    dt1[k][g] = x1.x * w.x + x1.y * w.y + x1.z * w.z + x1.w * w.w;
                }
            }
        };

        // register-resident c state
        float cr0[MAXU], cr1[MAXU];
#pragma unroll
        for (int k = 0; k < MAXU; k++) {
            int h = unit_h(k);
            cr0[k] = d_ct[((size_t)h << 10) + bI0];
            cr1[k] = d_ct[((size_t)h << 10) + bI1];
        }

        // wait for prep of t=1, then initial prefetch
        if (tid == 0) {
            volatile unsigned* q = &d_pfin[1];
            while (*q < (unsigned)NQ) __nanosleep(64);
            __threadfence();
        }
        __syncthreads();
        prefetch(1, 1);
        cp_wait<0>();
        __syncthreads();
        compute_dots(1, 1);

        float fc0 = 0.0f, fc1 = 0.0f;

        for (int t = 1; t < TT; t++) {
            const int buf = t & 1;
            // hx + readiness poll for t+1's rb
            if (wid == 0) {
                float s;
                if (t == 1) {
                    s = (lane == 0) ? d_hsum0 : 0.0f;
                    s = warpsum(s);
                } else {
                    const float* hp = d_hpart + (t - 1) * NGRP;
                    float p = __ldcg(&hp[lane]);
                    s = warpsum(p);
                }
                if (lane == 0) {
                    if (t + 1 < TT) {
                        volatile unsigned* q = &d_pfin[t + 1];
                        while (*q < (unsigned)NQ) __nanosleep(64);
                        __threadfence();
                    }
                    s_hx = s + d_evsum[t];
                }
            }
            __syncthreads();
            const float hx = s_hx;
            const int last = (t == TT - 1);

            if (!last) prefetch(t + 1, buf ^ 1);   // early: hides under cell math

            float hacc = 0.0f;
            auto cell = [&](int k) {
                float2 rb0 = s_rb[buf][k][0];
                float2 rb1 = s_rb[buf][k][1];
                float2 rb2 = s_rb[buf][k][2];
                float2 rb3 = s_rb[buf][k][3];
                float pre0 = fmaf(hx, rb0.x, rb0.y);
                float pre1 = fmaf(hx, rb1.x, rb1.y);
                float pre2 = fmaf(hx, rb2.x, rb2.y);
                float pre3 = fmaf(hx, rb3.x, rb3.y);
                float fw = last ? s_fw[buf][k] : 0.0f;
                {
                    float cn = sig_mufu(pre1 + dt0[k][1]) * cr0[k]
                             + sig_mufu(pre0 + dt0[k][0]) * tanh_mufu(pre2 + dt0[k][2]);
                    cr0[k] = cn;
                    float hn = sig_mufu(pre3 + dt0[k][3]) * tanh_mufu(cn);
                    if (last) fc0 += hn * fw; else hacc += hn;
                }
                {
                    float cn = sig_mufu(pre1 + dt1[k][1]) * cr1[k]
                             + sig_mufu(pre0 + dt1[k][0]) * tanh_mufu(pre2 + dt1[k][2]);
                    cr1[k] = cn;
                    float hn = sig_mufu(pre3 + dt1[k][3]) * tanh_mufu(cn);
                    if (last) fc1 += hn * fw; else hacc += hn;
                }
            };
#pragma unroll
            for (int k = 0; k < MAXU; k++) cell(k);

            if (!last) {
                float v = blockReduce256(hacc);
                if (tid == 0)
                    atomicAdd(&d_hpart[t * NGRP + (bid >> 3)], v);
                // ---- barrier ARRIVE ----
                if (tid == 0) {
                    __threadfence();
                    atomicAdd(&d_barcnt, 1u);
                }
                // ---- overlap: land prefetch, compute next step's dots ----
                cp_wait<0>();
                __syncthreads();
                compute_dots(t + 1, buf ^ 1);
                // ---- barrier WAIT ----
                ++epoch;
                if (tid == 0) {
                    volatile unsigned* p = &d_barcnt;
                    while (*p < epoch * (unsigned)NSTEP) __nanosleep(32);
                    __threadfence();
                }
                __syncthreads();
            }
        }

        atomicAdd(&out[bI0], fc0);
        atomicAdd(&out[bI1], fc1);

    } else {
        // ======================= PREP BLOCK (40 blocks) =======================
        for (int t = 1; t < TT; t++) {
            if (tid == 0) { s_ev = 0.0f; }
            __syncthreads();
            int myitems = 0;
            for (;;) {
                __syncthreads();
                if (tid == 0) s_base = (int)atomicAdd(&d_pq[t], 64u);
                __syncthreads();
                int base = s_base;
                if (base >= NQ) break;
                if (tid == 0) myitems += 64;           // NQ % 64 == 0
#pragma unroll
                for (int pair = 0; pair < 4; pair++) {
                    const int it0 = base + wid * 8 + pair * 2;
                    const float4* P[2];
                    int jj[2];
#pragma unroll
                    for (int k = 0; k < 2; k++) {
                        int it = it0 + k;
                        if (it < G4) {
                            jj[k] = t * G4 + it;
                            P[k] = (const float4*)(whh + (size_t)jj[k] * HH);
                        } else {
                            jj[k] = -1;
                            P[k] = (const float4*)(be + (size_t)(it - G4) * BE_BSTRIDE
                                                      + (size_t)t * HH);
                        }
                    }
                    float4 a0[6], a1[6];
#pragma unroll
                    for (int i = 0; i < 6; i++) {
                        a0[i] = P[0][lane + 32 * i];
                        a1[i] = P[1][lane + 32 * i];
                    }
                    float s0 = warpsum(sum6f4(a0));
                    float s1 = warpsum(sum6f4(a1));
                    if (lane == 0) {
                        if (jj[0] >= 0) d_rb[jj[0]] = make_float2(s0, bih[jj[0]] + bhh[jj[0]]);
                        else            atomicAdd(&s_ev, s0);
                        if (jj[1] >= 0) d_rb[jj[1]] = make_float2(s1, bih[jj[1]] + bhh[jj[1]]);
                        else            atomicAdd(&s_ev, s1);
                    }
                }
            }
            __syncthreads();
            if (tid == 0) {
                if (s_ev != 0.0f) atomicAdd(&d_evsum[t], s_ev);
                __threadfence();
                if (myitems) atomicAdd(&d_pfin[t], (unsigned)myitems);
            }
        }
    }

    // ---- end-of-launch cooperative self-reset (all 296 blocks) ----
    __syncthreads();
    if (tid == 0) {
        __threadfence();
        s_lastblk = (atomicAdd(&d_done, 1u) == NBLK - 1);
    }
    __syncthreads();
    if (s_lastblk) {
        if (tid == 0) { d_barcnt = 0u; d_gctr = 0u; d_done = 0u; d_hsum0 = 0.0f; }
        for (int i = tid; i < TT; i += 256) {
            d_pq[i] = 0u; d_pfin[i] = 0u; d_evsum[i] = 0.0f;
        }
        for (int i = tid; i < TT * NGRP; i += 256) d_hpart[i] = 0.0f;
        __syncthreads();
        if (tid == 0) __threadfence();
    }
}

// ---------------- launcher ----------------
extern "C" void kernel_launch(void* const* d_in, const int* in_sizes, int n_in,
                              void* d_out, int out_size) {
    const float* bp  = (const float*)d_in[0];
    const float* be  = (const float*)d_in[1];
    const float* wih = (const float*)d_in[2];
    const float* whh = (const float*)d_in[3];
    const float* bih = (const float*)d_in[4];
    const float* bhh = (const float*)d_in[5];
    const float* fcw = (const float*)d_in[6];
    const float* fcb = (const float*)d_in[7];
    float* out = (float*)d_out;

    cudaFuncSetAttribute(fused_kernel,
                         cudaFuncAttributeMaxDynamicSharedMemorySize, FUSED_SMEM);

    fused_kernel<<<NBLK, 256, FUSED_SMEM>>>(bp, be, wih, whh, bih, bhh, fcw, fcb, out);
}

// round 17
// speedup vs baseline: 1.3950x; 1.3950x over previous
#include <cuda_runtime.h>
#include <cuda_bf16.h>
#include <math.h>
#include <stdint.h>

// Problem constants
#define TT 20
#define DIN 4
#define HH 768
#define BB 1024
#define G4 (4*HH)           // 3072
#define BE_BSTRIDE (TT*HH)  // 15360
#define BP_BSTRIDE (TT*DIN) // 80
#define NBLK 296            // 2 blocks/SM x 148 SMs
#define NGRP 37             // hsum partial slots (bid>>3)
#define NRS   (19*G4)       // rowsum items: 58368
#define NPREP (NRS + 19*BB) // + evsum items: 77824
#define MAXU 6              // 5 base units + 1 optional extra
#define NTILE 192           // step-0 gemm tiles

// ---------------- device scratch ----------------
__device__ float  d_ct[HH * BB];           // c handoff from step-0, [h][b]
__device__ float2 d_rb[TT * G4];           // {rowsum, biassum} packed
__device__ float4 d_bpT[TT * BB];          // batch_price transposed [t][b]
__device__ float  d_evsum[TT];
__device__ float  d_hsum0;                 // step-0 h sum (gemm epilogue)
__device__ float  d_hpart[TT * NGRP];      // per-step per-group hsum partials
__device__ unsigned d_barcnt;              // monotonic barrier counter (k2)
__device__ unsigned d_pctr;                // prep work-steal counter (k1)
__device__ unsigned d_gctr;                // gemm tile work-steal counter (k1)
__device__ unsigned d_done1, d_done2;

// ---------------- helpers ----------------
__device__ __forceinline__ float fast_sigmoid(float x) {        // accurate (gemm)
    return __fdividef(1.0f, 1.0f + __expf(-x));
}
__device__ __forceinline__ float fast_tanh(float x) {           // accurate (gemm)
    return __fdividef(2.0f, 1.0f + __expf(-2.0f * x)) - 1.0f;
}
__device__ __forceinline__ float tanh_mufu(float x) {           // MUFU.TANH
    float r; asm("tanh.approx.f32 %0, %1;" : "=f"(r) : "f"(x)); return r;
}
__device__ __forceinline__ uint32_t f2tf32(float f) {
    uint32_t r; asm("cvt.rna.tf32.f32 %0, %1;" : "=r"(r) : "f"(f)); return r;
}
__device__ __forceinline__ uint32_t smem_u32(const void* p) {
    return (uint32_t)__cvta_generic_to_shared(p);
}
__device__ __forceinline__ void cp_async16(uint32_t dst, const void* src) {
    asm volatile("cp.async.ca.shared.global [%0], [%1], 16;" :: "r"(dst), "l"(src));
}
__device__ __forceinline__ void cp_async8(uint32_t dst, const void* src) {
    asm volatile("cp.async.ca.shared.global [%0], [%1], 8;" :: "r"(dst), "l"(src));
}
__device__ __forceinline__ void cp_async4(uint32_t dst, const void* src) {
    asm volatile("cp.async.ca.shared.global [%0], [%1], 4;" :: "r"(dst), "l"(src));
}
__device__ __forceinline__ void cp_commit() {
    asm volatile("cp.async.commit_group;");
}
template<int N>
__device__ __forceinline__ void cp_wait() {
    asm volatile("cp.async.wait_group %0;" :: "n"(N));
}
__device__ __forceinline__ float blockReduce256(float v) {
    __shared__ float red[8];
    int lane = threadIdx.x & 31, wid = threadIdx.x >> 5;
#pragma unroll
    for (int o = 16; o; o >>= 1) v += __shfl_down_sync(0xffffffffu, v, o);
    if (lane == 0) red[wid] = v;
    __syncthreads();
    if (wid == 0) {
        v = (lane < 8) ? red[lane] : 0.0f;
#pragma unroll
        for (int o = 4; o; o >>= 1) v += __shfl_down_sync(0xffffffffu, v, o);
    }
    __syncthreads();
    return v;
}
__device__ __forceinline__ float sum6f4(const float4 a[6]) {
    float s = 0.0f;
#pragma unroll
    for (int i = 0; i < 6; i++) s += (a[i].x + a[i].y) + (a[i].z + a[i].w);
    return s;
}
__device__ __forceinline__ float warpsum(float s) {
#pragma unroll
    for (int o = 16; o; o >>= 1) s += __shfl_down_sync(0xffffffffu, s, o);
    return s;
}
// extra (6th) unit: heavy blocks land on 56 DISTINCT SMs
__device__ __forceinline__ int extra_unit(int bid) {
    if (bid < 28) return 1480 + bid;
    if (bid >= 176 && bid < 204) return 1332 + bid;   // 1508..1535
    return -1;
}

// ---------------- GEMM tile (tf32 mma), step 0, fused activations ----------
#define GBM 128
#define GBH 32
#define GBN 96
#define GBK 16
#define ASTR 20
#define BSTR 20
#define GSTR 132
#define K1_SMEM (GBN * GSTR * 4)   // 50688 B dynamic

__device__ __forceinline__ void gemm_tile(
        int hblk, int mblk,
        const float* __restrict__ be,  const float* __restrict__ whh,
        const float* __restrict__ bp,  const float* __restrict__ wih,
        const float* __restrict__ bih, const float* __restrict__ bhh,
        uint32_t* sm_u) {
    uint32_t* smA = sm_u;
    uint32_t* smB = sm_u + 2 * GBM * ASTR;
    float*    gsm = (float*)sm_u;

    const int tid  = threadIdx.x;
    const int lane = tid & 31;
    const int wid  = tid >> 5;
    const int wm   = wid >> 1;
    const int wn   = wid & 1;
    const int r    = lane >> 2;
    const int cl   = lane & 3;
    const int m0   = mblk * GBM;

    const int arow0 = tid >> 2;
    const int ac4   = tid & 3;
    const int brow  = tid >> 2;
    const int brow2 = (tid + 256) >> 2;
    auto growf = [&] (int row) {
        int q = row >> 5;
        int g = (q == 0) ? 0 : (q == 1 ? 2 : 3);
        return g * HH + hblk * GBH + (row & 31);
    };
    const int grow1 = growf(brow);
    const int grow2 = growf(brow2 < GBN ? brow2 : 0);
    const bool bpred2 = (brow2 < GBN);

    float acc[2][6][4];
#pragma unroll
    for (int i = 0; i < 2; i++)
#pragma unroll
        for (int j = 0; j < 6; j++)
#pragma unroll
            for (int q = 0; q < 4; q++) acc[i][j][q] = 0.0f;

    float4 ra[2], rb[2];
    auto ldg = [&](int kt) {
        ra[0] = *(const float4*)(be + (size_t)(m0 + arow0) * BE_BSTRIDE + kt * GBK + ac4 * 4);
        ra[1] = *(const float4*)(be + (size_t)(m0 + arow0 + 64) * BE_BSTRIDE + kt * GBK + ac4 * 4);
        rb[0] = *(const float4*)(whh + (size_t)grow1 * HH + kt * GBK + ac4 * 4);
        if (bpred2)
            rb[1] = *(const float4*)(whh + (size_t)grow2 * HH + kt * GBK + ac4 * 4);
    };
    auto sts = [&](int buf) {
        uint32_t* pa = smA + buf * (GBM * ASTR);
        uint32_t* pb = smB + buf * (GBN * BSTR);
        uint4 v;
        v.x = f2tf32(ra[0].x); v.y = f2tf32(ra[0].y); v.z = f2tf32(ra[0].z); v.w = f2tf32(ra[0].w);
        *(uint4*)(pa + arow0 * ASTR + ac4 * 4) = v;
        v.x = f2tf32(ra[1].x); v.y = f2tf32(ra[1].y); v.z = f2tf32(ra[1].z); v.w = f2tf32(ra[1].w);
        *(uint4*)(pa + (arow0 + 64) * ASTR + ac4 * 4) = v;
        v.x = f2tf32(rb[0].x); v.y = f2tf32(rb[0].y); v.z = f2tf32(rb[0].z); v.w = f2tf32(rb[0].w);
        *(uint4*)(pb + brow * BSTR + ac4 * 4) = v;
        if (bpred2) {
            v.x = f2tf32(rb[1].x); v.y = f2tf32(rb[1].y); v.z = f2tf32(rb[1].z); v.w = f2tf32(rb[1].w);
            *(uint4*)(pb + brow2 * BSTR + ac4 * 4) = v;
        }
    };

    ldg(0);
    sts(0);
    __syncthreads();

    const int NKT = HH / GBK;   // 48
    for (int kt = 0; kt < NKT; kt++) {
        int buf = kt & 1;
        if (kt < NKT - 1) ldg(kt + 1);

        const uint32_t* pa = smA + buf * (GBM * ASTR);
        const uint32_t* pb = smB + buf * (GBN * BSTR);
#pragma unroll
        for (int kk = 0; kk < 2; kk++) {
            const int kof = kk * 8;
            uint32_t af[2][4], bf[6][2];
#pragma unroll
            for (int i = 0; i < 2; i++) {
                int m = wm * 32 + i * 16 + r;
                af[i][0] = pa[m * ASTR + kof + cl];
                af[i][1] = pa[(m + 8) * ASTR + kof + cl];
                af[i][2] = pa[m * ASTR + kof + cl + 4];
                af[i][3] = pa[(m + 8) * ASTR + kof + cl + 4];
            }
#pragma unroll
            for (int j = 0; j < 6; j++) {
                int n = wn * 48 + j * 8 + r;
                bf[j][0] = pb[n * BSTR + kof + cl];
                bf[j][1] = pb[n * BSTR + kof + cl + 4];
            }
#pragma unroll
            for (int i = 0; i < 2; i++)
#pragma unroll
                for (int j = 0; j < 6; j++) {
                    asm volatile(
                        "mma.sync.aligned.m16n8k8.row.col.f32.tf32.tf32.f32 "
                        "{%0,%1,%2,%3}, {%4,%5,%6,%7}, {%8,%9}, {%0,%1,%2,%3};"
                        : "+f"(acc[i][j][0]), "+f"(acc[i][j][1]),
                          "+f"(acc[i][j][2]), "+f"(acc[i][j][3])
                        : "r"(af[i][0]), "r"(af[i][1]), "r"(af[i][2]), "r"(af[i][3]),
                          "r"(bf[j][0]), "r"(bf[j][1]));
                }
        }
        if (kt < NKT - 1) {
            sts(buf ^ 1);
            __syncthreads();
        }
    }

    __syncthreads();
#pragma unroll
    for (int i = 0; i < 2; i++)
#pragma unroll
        for (int j = 0; j < 6; j++) {
            int m = wm * 32 + i * 16 + r;
            int n = wn * 48 + j * 8 + 2 * cl;
            gsm[n * GSTR + m]           = acc[i][j][0];
            gsm[(n + 1) * GSTR + m]     = acc[i][j][1];
            gsm[n * GSTR + m + 8]       = acc[i][j][2];
            gsm[(n + 1) * GSTR + m + 8] = acc[i][j][3];
        }
    __syncthreads();

    const int m = tid & 127;
    const int b = m0 + m;
    const float4 x = *(const float4*)(bp + (size_t)b * BP_BSTRIDE);  // t=0
    float hpart = 0.0f;
#pragma unroll
    for (int it = 0; it < 16; it++) {
        int hl = (tid >> 7) + it * 2;
        int hg = hblk * GBH + hl;
        int ri = hg, rg = 2 * HH + hg, ro = 3 * HH + hg;
        float4 wi = ((const float4*)wih)[ri];
        float4 wg = ((const float4*)wih)[rg];
        float4 wo = ((const float4*)wih)[ro];
        float gi = gsm[hl * GSTR + m]        + bih[ri] + bhh[ri]
                 + x.x * wi.x + x.y * wi.y + x.z * wi.z + x.w * wi.w;
        float gg = gsm[(hl + 32) * GSTR + m] + bih[rg] + bhh[rg]
                 + x.x * wg.x + x.y * wg.y + x.z * wg.z + x.w * wg.w;
        float go = gsm[(hl + 64) * GSTR + m] + bih[ro] + bhh[ro]
                 + x.x * wo.x + x.y * wo.y + x.z * wo.z + x.w * wo.w;
        float cn = fast_sigmoid(gi) * fast_tanh(gg);   // c_prev = 0, f-gate dead
        d_ct[(size_t)hg * BB + b] = cn;
        hpart += fast_sigmoid(go) * fast_tanh(cn);
    }
    float v = blockReduce256(hpart);
    if (tid == 0) atomicAdd(&d_hsum0, v);
}

// ================= kernel 1: GEMM + prep =================================
__global__ __launch_bounds__(256, 2) void prep_kernel(
        const float* __restrict__ bp,  const float* __restrict__ be,
        const float* __restrict__ wih, const float* __restrict__ whh,
        const float* __restrict__ bih, const float* __restrict__ bhh,
        const float* __restrict__ fcb, float* __restrict__ out) {
    extern __shared__ uint32_t sm_u[];
    __shared__ float s_ev[TT];
    __shared__ volatile int s_base;
    __shared__ volatile int s_tile;

    const int tid  = threadIdx.x;
    const int bid  = blockIdx.x;
    const int lane = tid & 31;
    const int wid  = tid >> 5;

    if (tid < TT) s_ev[tid] = 0.0f;
    if (bid == 0) {
        float fb = fcb[0];
        for (int i = tid; i < BB; i += 256) out[i] = fb;
    }
    for (int idx = bid * 256 + tid; idx < TT * BB; idx += NBLK * 256) {
        int t = idx >> 10, b = idx & (BB - 1);
        d_bpT[idx] = *(const float4*)(bp + (size_t)b * BP_BSTRIDE + t * DIN);
    }
    __syncthreads();

    // step-0 GEMM tiles, work-stolen
    for (;;) {
        if (tid == 0) s_tile = (int)atomicAdd(&d_gctr, 1u);
        __syncthreads();
        int tile = s_tile;
        if (tile >= NTILE) break;
        gemm_tile(tile % 24, tile / 24, be, whh, bp, wih, bih, bhh, sm_u);
        __syncthreads();
    }

    // rowsums / evsums, work-stolen (streaming loads: no L2 reuse)
    for (;;) {
        __syncthreads();
        if (tid == 0) s_base = (int)atomicAdd(&d_pctr, 64u);
        __syncthreads();
        int base = s_base;
        if (base >= NPREP) break;
#pragma unroll
        for (int pair = 0; pair < 4; pair++) {
            const int it0 = base + wid * 8 + pair * 2;
            const float4* P[2];
            int jj[2], tt[2];
#pragma unroll
            for (int k = 0; k < 2; k++) {
                int it = it0 + k;
                if (it >= NPREP) it = NPREP - 1;
                if (it < NRS) {
                    jj[k] = G4 + it;
                    tt[k] = 0;
                    P[k] = (const float4*)(whh + (size_t)jj[k] * HH);
                } else {
                    int rr = it - NRS;
                    jj[k] = -1;
                    tt[k] = 1 + (rr >> 10);
                    P[k] = (const float4*)(be + (size_t)(rr & (BB - 1)) * BE_BSTRIDE
                                              + (size_t)tt[k] * HH);
                }
            }
            bool live0 = (it0 < NPREP);
            bool live1 = (it0 + 1 < NPREP);
            float4 a0[6], a1[6];
#pragma unroll
            for (int i = 0; i < 6; i++) {
                a0[i] = __ldcs(&P[0][lane + 32 * i]);
                a1[i] = __ldcs(&P[1][lane + 32 * i]);
            }
            float s0 = warpsum(sum6f4(a0));
            float s1 = warpsum(sum6f4(a1));
            if (lane == 0) {
                if (live0) {
                    if (jj[0] >= 0) d_rb[jj[0]] = make_float2(s0, bih[jj[0]] + bhh[jj[0]]);
                    else            atomicAdd(&s_ev[tt[0]], s0);
                }
                if (live1) {
                    if (jj[1] >= 0) d_rb[jj[1]] = make_float2(s1, bih[jj[1]] + bhh[jj[1]]);
                    else            atomicAdd(&s_ev[tt[1]], s1);
                }
            }
        }
    }
    __syncthreads();
    if (tid < 19) {
        float v = s_ev[tid + 1];
        if (v != 0.0f) atomicAdd(&d_evsum[tid + 1], v);
    }
    __syncthreads();
    if (tid == 0) {
        __threadfence();
        if (atomicAdd(&d_done1, 1u) == NBLK - 1) {
            d_pctr = 0u; d_gctr = 0u; d_done1 = 0u;
            __threadfence();
        }
    }
}

// ================= kernel 2: 19 recurrent steps (persistent) ==============
__global__ __launch_bounds__(256, 2) void step_kernel(
        const float* __restrict__ wih, const float* __restrict__ fcw,
        float* __restrict__ out) {
    __shared__ float4 s_w[2][MAXU][4];
    __shared__ float2 s_rb[2][MAXU][4];
    __shared__ float  s_fw[2][MAXU];
    __shared__ float  s_hx;
    __shared__ int    s_lastblk;

    const int tid  = threadIdx.x;
    const int bid  = blockIdx.x;
    const int grp  = bid >> 3;
    const int lane = tid & 31;
    const int wid  = tid >> 5;

    const int half = bid & 1;
    const int bI0  = (half << 9) + tid;
    const int bI1  = bI0 + 256;
    const float4* wih4 = (const float4*)wih;
    const int xu   = extra_unit(bid);

    auto unit_h = [&](int k) -> int {
        return (k < 5) ? ((k * NBLK + bid) >> 1) : (xu >> 1);
    };
    auto prefetch = [&](int t, int buf) {
        const int base = t * G4;
        if (tid < MAXU * 4) {
            int k = tid >> 2, g = tid & 3;
            if (k < 5 || xu >= 0)
                cp_async16(smem_u32(&s_w[buf][k][g]), &wih4[base + g * HH + unit_h(k)]);
        } else if (tid >= 32 && tid < 32 + MAXU * 4) {
            int j = tid - 32; int k = j >> 2, g = j & 3;
            if (k < 5 || xu >= 0)
                cp_async8(smem_u32(&s_rb[buf][k][g]), &d_rb[base + g * HH + unit_h(k)]);
        } else if (tid >= 64 && tid < 64 + MAXU) {
            int k = tid - 64;
            if (k < 5 || xu >= 0)
                cp_async4(smem_u32(&s_fw[buf][k]), fcw + unit_h(k));
        }
        cp_commit();
    };

    // Shadow precompute: dtb = (x.W + bias) * sc, sc = 0.5 for sigmoid gates
    // (i,f,o), 1 for the tanh (g) gate. Window then needs ONE fmaf per gate:
    //   sigmoid input*0.5 = fmaf(0.5*hx, rs, dtb)   tanh input = fmaf(hx, rs, dtb)
    float dt0[MAXU][4], dt1[MAXU][4];
    auto compute_dots = [&](int t, int buf) {
        float4 x0 = d_bpT[(t << 10) + bI0];
        float4 x1 = d_bpT[(t << 10) + bI1];
#pragma unroll
        for (int k = 0; k < MAXU; k++) {
#pragma unroll
            for (int g = 0; g < 4; g++) {
                float4 w = s_w[buf][k][g];
                float  bsy = s_rb[buf][k][g].y;
                float  sc = (g == 2) ? 1.0f : 0.5f;
                float d0 = x0.x * w.x + x0.y * w.y + x0.z * w.z + x0.w * w.w;
                float d1 = x1.x * w.x + x1.y * w.y + x1.z * w.z + x1.w * w.w;
                dt0[k][g] = (d0 + bsy) * sc;
                dt1[k][g] = (d1 + bsy) * sc;
            }
        }
    };

    // register-resident c state
    float cr0[MAXU], cr1[MAXU];
#pragma unroll
    for (int k = 0; k < MAXU; k++) {
        if (k < 5 || xu >= 0) {
            int h = unit_h(k);
            cr0[k] = d_ct[((size_t)h << 10) + bI0];
            cr1[k] = d_ct[((size_t)h << 10) + bI1];
        } else { cr0[k] = 0.0f; cr1[k] = 0.0f; }
    }

    prefetch(1, 1);
    cp_wait<0>();
    __syncthreads();
    compute_dots(1, 1);

    float fc0 = 0.0f, fc1 = 0.0f;

    for (int t = 1; t < TT; t++) {
        const int buf = t & 1;
        if (wid == 0) {
            float s;
            if (t == 1) {
                s = (lane == 0) ? d_hsum0 : 0.0f;
                s = warpsum(s);
            } else {
                const float* hp = d_hpart + (t - 1) * NGRP;
                float p = __ldcg(&hp[lane]);
                if (lane < NGRP - 32) p += __ldcg(&hp[32 + lane]);
                s = warpsum(p);
            }
            if (lane == 0) s_hx = s + d_evsum[t];
        }
        __syncthreads();
        const float hx   = s_hx;
        const float hx05 = 0.5f * hx;
        const int last = (t == TT - 1);

        if (!last) prefetch(t + 1, buf ^ 1);   // early issue, hides under math

        float hacc = 0.0f;
        auto cell = [&](int k) {
            float rs0 = s_rb[buf][k][0].x;
            float rs1 = s_rb[buf][k][1].x;
            float rs2 = s_rb[buf][k][2].x;
            float rs3 = s_rb[buf][k][3].x;
            float fw = last ? s_fw[buf][k] : 0.0f;
            {
                float ti = tanh_mufu(fmaf(hx05, rs0, dt0[k][0]));
                float tf = tanh_mufu(fmaf(hx05, rs1, dt0[k][1]));
                float tg = tanh_mufu(fmaf(hx,   rs2, dt0[k][2]));
                float to = tanh_mufu(fmaf(hx05, rs3, dt0[k][3]));
                float cn = fmaf(tf, 0.5f, 0.5f) * cr0[k]
                         + fmaf(ti, 0.5f, 0.5f) * tg;
                cr0[k] = cn;
                float hn = fmaf(to, 0.5f, 0.5f) * tanh_mufu(cn);
                if (last) fc0 += hn * fw; else hacc += hn;
            }
            {
                float ti = tanh_mufu(fmaf(hx05, rs0, dt1[k][0]));
                float tf = tanh_mufu(fmaf(hx05, rs1, dt1[k][1]));
                float tg = tanh_mufu(fmaf(hx,   rs2, dt1[k][2]));
                float to = tanh_mufu(fmaf(hx05, rs3, dt1[k][3]));
                float cn = fmaf(tf, 0.5f, 0.5f) * cr1[k]
                         + fmaf(ti, 0.5f, 0.5f) * tg;
                cr1[k] = cn;
                float hn = fmaf(to, 0.5f, 0.5f) * tanh_mufu(cn);
                if (last) fc1 += hn * fw; else hacc += hn;
            }
        };
#pragma unroll
        for (int k = 0; k < 5; k++) cell(k);
        if (xu >= 0) cell(5);

        if (!last) {
            float v = blockReduce256(hacc);
            if (tid == 0)
                atomicAdd(&d_hpart[t * NGRP + grp], v);
            if (tid == 0) {
                __threadfence();
                atomicAdd(&d_barcnt, 1u);
            }
            cp_wait<0>();
            __syncthreads();
            compute_dots(t + 1, buf ^ 1);
            if (tid == 0) {
                volatile unsigned* p = &d_barcnt;
                while (*p < (unsigned)(t * NBLK)) __nanosleep(32);
                __threadfence();
            }
            __syncthreads();
        }
    }

    atomicAdd(&out[bI0], fc0);
    atomicAdd(&out[bI1], fc1);

    __syncthreads();
    if (tid == 0) {
        __threadfence();
        s_lastblk = (atomicAdd(&d_done2, 1u) == NBLK - 1);
    }
    __syncthreads();
    if (s_lastblk) {
        if (tid == 0) { d_barcnt = 0u; d_done2 = 0u; d_hsum0 = 0.0f; }
        for (int i = tid; i < TT; i += 256) d_evsum[i] = 0.0f;
        for (int i = tid; i < TT * NGRP; i += 256) d_hpart[i] = 0.0f;
        __syncthreads();
        if (tid == 0) __threadfence();
    }
}

// ---------------- launcher ----------------
extern "C" void kernel_launch(void* const* d_in, const int* in_sizes, int n_in,
                              void* d_out, int out_size) {
    const float* bp  = (const float*)d_in[0];
    const float* be  = (const float*)d_in[1];
    const float* wih = (const float*)d_in[2];
    const float* whh = (const float*)d_in[3];
    const float* bih = (const float*)d_in[4];
    const float* bhh = (const float*)d_in[5];
    const float* fcw = (const float*)d_in[6];
    const float* fcb = (const float*)d_in[7];
    float* out = (float*)d_out;

    cudaFuncSetAttribute(prep_kernel,
                         cudaFuncAttributeMaxDynamicSharedMemorySize, K1_SMEM);

    prep_kernel<<<NBLK, 256, K1_SMEM>>>(bp, be, wih, whh, bih, bhh, fcb, out);
    step_kernel<<<NBLK, 256>>>(wih, fcw, out);
}